// round 16
// baseline (speedup 1.0000x reference)
#include <cuda_runtime.h>

// SRLEmbeddings: B=16,S=32,L=256,D=768,P=16,T=4, PAD=1
// SINGLE-PASS design: each embedding byte crosses DRAM exactly once.
// Grid 512 = one CTA per (b,s); block 768 = 192 float4 col-groups x 4 rowlanes.
// 1 CTA/SM (172KB smem). Phase 1: 48 scanners build PER-ROW event lists
// rev[pos] = {(pair|cnt<<8)...}. Phase 2: stream active rows with next-batch
// prefetch; for each row, scatter into smem acc via bank-conflict-free
// component-transposed atomics (acc[4][48][192]). Phase 3: epilogue writes
// sentence avg + all 48 pair outputs straight from smem (STG.128, coalesced).

#define NB 16
#define NS 32
#define NL 256
#define ND 768
#define ND4 (ND / 4)
#define NP 16
#define NT 4
#define NPAIR 48
#define PAD_ID 1
#define NTHREADS 768
#define NCG 192
#define NRL 4
#define REVCAP 16

// smem: acc 147456 | stage 12288 | rev 8192 | alist 1024 | sid 1024 | revn 1024 | span 768 | den 192 | nact 16
#define SMEM_BYTES (147456 + 12288 + 8192 + 1024 + 1024 + 1024 + 768 + 192 + 16)

__global__ __launch_bounds__(NTHREADS, 1)
void srl_kernel(const int* __restrict__ sent_ids,
                const int* __restrict__ attn,
                const int* __restrict__ pred_ids,
                const int* __restrict__ arg0_ids,
                const int* __restrict__ arg1_ids,
                const float* __restrict__ emb,
                float* __restrict__ out)
{
    extern __shared__ char smem_raw[];
    float*          acc    = (float*)smem_raw;                 // [4][NPAIR][NCG] comp-transposed
    float4*         stage  = (float4*)(acc + 4 * NPAIR * NCG); // [NRL][NCG]
    unsigned short* rev    = (unsigned short*)(stage + NRL * NCG); // [NL][REVCAP] pair|cnt<<8
    int*            alist  = (int*)(rev + NL * REVCAP);        // [NL]
    int*            sid_s  = alist + NL;                       // [NL]
    int*            revn   = sid_s + NL;                       // [NL] events per alist pos
    int*            span_s = revn + NL;                        // [NPAIR][NT]
    int*            den_s  = span_s + NPAIR * NT;              // [NPAIR]
    int*            nact_s = den_s + NPAIR;

    const int bs   = blockIdx.x;
    const int tid  = threadIdx.x;
    const int lane = tid & 31;
    const int cg   = tid % NCG;     // float4 col group
    const int rl   = tid / NCG;     // rowlane 0..3

    // ---- phase 0: init + metadata ----
    #pragma unroll
    for (int k = 0; k < 12; k++)            // 9216 float4 of acc
        ((float4*)acc)[tid + k * NTHREADS] = make_float4(0.f, 0.f, 0.f, 0.f);
    if (tid < NL) {
        sid_s[tid] = sent_ids[bs * NL + tid];
        revn[tid]  = 0;
    }
    if (tid < NPAIR * NT) {
        int arg = tid / (NP * NT);
        int rem = tid % (NP * NT);
        const int* src = (arg == 0) ? pred_ids : ((arg == 1) ? arg0_ids : arg1_ids);
        span_s[tid] = src[bs * NP * NT + rem];
    }
    if (tid < 32) {   // warp 0: ballot compaction (ascending, deterministic)
        int base = 0;
        #pragma unroll
        for (int c = 0; c < NL / 32; c++) {
            int l = c * 32 + lane;
            int a = attn[bs * NL + l];
            unsigned m = __ballot_sync(0xFFFFFFFFu, a != 0);
            if (a != 0) alist[base + __popc(m & ((1u << lane) - 1u))] = l;
            base += __popc(m);
        }
        if (lane == 0) nact_s[0] = base;
    }
    __syncthreads();

    const int nact = nact_s[0];

    // ---- phase 1: 48 scanners -> per-ROW event lists ----
    if (tid < NPAIR) {
        int v0 = span_s[tid * NT + 0];
        int v1 = span_s[tid * NT + 1];
        int v2 = span_s[tid * NT + 2];
        int v3 = span_s[tid * NT + 3];
        int den = 0;
        #pragma unroll 1
        for (int i = 0; i < nact; i++) {
            int sid = sid_s[alist[i]];
            int c = (v0 == sid && v0 != PAD_ID)
                  + (v1 == sid && v1 != PAD_ID)
                  + (v2 == sid && v2 != PAD_ID)
                  + (v3 == sid && v3 != PAD_ID);
            if (c) {
                int pos = atomicAdd(&revn[i], 1);
                if (pos < REVCAP) rev[i * REVCAP + pos] = (unsigned short)(tid | (c << 8));
                den += c;
            }
        }
        den_s[tid] = den;
    }
    __syncthreads();

    // ---- phase 2: stream + scatter, next-batch prefetch (16 rows/batch) ----
    const float4* eb = (const float4*)(emb + (size_t)bs * NL * ND) + cg;
    float4 s4 = make_float4(0.f, 0.f, 0.f, 0.f);
    const int clampi = (nact > 0) ? nact - 1 : 0;

    float4 vc[4]; int idxc[4];
    #pragma unroll
    for (int k = 0; k < 4; k++) {           // prime batch 0
        idxc[k] = NRL * k + rl;
        int l = alist[min(idxc[k], clampi)];
        vc[k] = (nact > 0) ? __ldg(eb + (size_t)l * ND4) : make_float4(0.f,0.f,0.f,0.f);
    }

    #pragma unroll 1
    for (int i0 = 0; i0 < nact; i0 += 16) {
        float4 vn[4]; int idxn[4];
        #pragma unroll
        for (int k = 0; k < 4; k++) {       // prefetch next batch
            idxn[k] = i0 + 16 + NRL * k + rl;
            int l = alist[min(idxn[k], clampi)];
            vn[k] = __ldg(eb + (size_t)l * ND4);
        }
        #pragma unroll
        for (int k = 0; k < 4; k++) {       // consume current batch
            if (idxc[k] < nact) {
                float4 v = vc[k];
                s4.x += v.x; s4.y += v.y; s4.z += v.z; s4.w += v.w;
                int rn = revn[idxc[k]];
                #pragma unroll 1
                for (int e = 0; e < rn; e++) {
                    unsigned ev = rev[idxc[k] * REVCAP + e];
                    int   pr = (int)(ev & 0xFFu);
                    float c  = (float)(ev >> 8);
                    float* a = acc + pr * NCG + cg;
                    atomicAdd(a,                     c * v.x);
                    atomicAdd(a + NPAIR * NCG,       c * v.y);
                    atomicAdd(a + 2 * NPAIR * NCG,   c * v.z);
                    atomicAdd(a + 3 * NPAIR * NCG,   c * v.w);
                }
            }
        }
        #pragma unroll
        for (int k = 0; k < 4; k++) { vc[k] = vn[k]; idxc[k] = idxn[k]; }
    }

    stage[rl * NCG + cg] = s4;
    __syncthreads();    // acc + stage complete

    // ---- phase 3: epilogue ----
    if (rl == 0) {      // sentence average
        float4 a = stage[cg],           b = stage[NCG + cg];
        float4 c = stage[2 * NCG + cg], d = stage[3 * NCG + cg];
        float tc = fmaxf((float)nact, 1.0f);
        float4 o;
        o.x = (a.x + b.x + c.x + d.x) / tc;
        o.y = (a.y + b.y + c.y + d.y) / tc;
        o.z = (a.z + b.z + c.z + d.z) / tc;
        o.w = (a.w + b.w + c.w + d.w) / tc;
        ((float4*)(out + (size_t)bs * ND))[cg] = o;
    }

    float* outp = out + (size_t)NB * NS * ND;
    #pragma unroll 1
    for (int j = 0; j < NPAIR / NRL; j++) { // 12 pairs per rowlane
        int pair = rl * (NPAIR / NRL) + j;
        int den  = den_s[pair];
        float inv = (den > 0) ? 1.0f / (float)den : 0.0f;
        const float* a = acc + pair * NCG + cg;
        float4 o;
        o.x = a[0]                 * inv;
        o.y = a[NPAIR * NCG]       * inv;
        o.z = a[2 * NPAIR * NCG]   * inv;
        o.w = a[3 * NPAIR * NCG]   * inv;
        int arg = pair >> 4;
        int p   = pair & 15;
        float4* o4 = (float4*)(outp + (size_t)arg * NB * NS * NP * ND
                                    + (size_t)bs * NP * ND
                                    + (size_t)p * ND);
        o4[cg] = o;
    }
}

extern "C" void kernel_launch(void* const* d_in, const int* in_sizes, int n_in,
                              void* d_out, int out_size)
{
    const int*   sent_ids = (const int*)d_in[0];
    const int*   attn     = (const int*)d_in[1];
    const int*   pred_ids = (const int*)d_in[2];
    const int*   arg0_ids = (const int*)d_in[3];
    const int*   arg1_ids = (const int*)d_in[4];
    const float* emb      = (const float*)d_in[5];
    float*       out      = (float*)d_out;

    cudaFuncSetAttribute(srl_kernel, cudaFuncAttributeMaxDynamicSharedMemorySize, SMEM_BYTES);

    dim3 grid(NB * NS);
    dim3 block(NTHREADS);
    srl_kernel<<<grid, block, SMEM_BYTES>>>(sent_ids, attn, pred_ids, arg0_ids,
                                            arg1_ids, emb, out);
}

// round 17
// speedup vs baseline: 3.0226x; 3.0226x over previous
#include <cuda_runtime.h>

// SRLEmbeddings: B=16,S=32,L=256,D=768,P=16,T=4, PAD=1
// Fused-interleaved kernel. Grid 512 = one CTA per (b,s).
// Block 384 = 192 float4 col-groups x 2 row-lanes. 4 CTAs/SM -> one wave.
// Phase 1: PARALLEL event build (48 pairs x 8 segments, deterministic).
// Main loop: per 8-row stream batch, ALSO fully gather 2 pairs between the
// stream loads and their consumption -> DRAM + L2 loads overlap in flight;
// the old ~20us L2-bound phase-3 tail hides under the DRAM-bound stream.

#define NB 16
#define NS 32
#define NL 256
#define ND 768
#define ND4 (ND / 4)
#define NP 16
#define NT 4
#define NPAIR 48
#define PAD_ID 1
#define NTHREADS 384
#define NCG 192
#define NRL 2
#define EVCAP 16
#define NSEG 8
#define SEGCAP 16

__global__ __launch_bounds__(NTHREADS, 4)
void srl_kernel(const int* __restrict__ sent_ids,
                const int* __restrict__ attn,
                const int* __restrict__ pred_ids,
                const int* __restrict__ arg0_ids,
                const int* __restrict__ arg1_ids,
                const float* __restrict__ emb,
                float* __restrict__ out)
{
    __shared__ unsigned short evseg[NPAIR * NSEG * SEGCAP];  // 12288 B
    __shared__ unsigned char  cntseg[NPAIR * NSEG];          //   384 B
    __shared__ unsigned short events[NPAIR * EVCAP];         //  1536 B (l | cnt<<8)
    __shared__ int            nev_s[NPAIR];
    __shared__ float          inv_s[NPAIR];
    __shared__ int            alist[NL];
    __shared__ int            sid_s[NL];
    __shared__ int            span_s[NPAIR * NT];
    __shared__ float4         stage[NRL * NCG];              //  6144 B
    __shared__ int            nact_s;

    const int bs   = blockIdx.x;
    const int tid  = threadIdx.x;
    const int lane = tid & 31;
    const int cg   = tid % NCG;     // float4 col group (full 768 cols)
    const int rl   = tid / NCG;     // row lane 0..1

    // ---- phase 0: metadata ----
    if (tid < NL) sid_s[tid] = sent_ids[bs * NL + tid];
    if (tid < NPAIR * NT) {         // 192 ints
        int arg = tid / (NP * NT);
        int rem = tid % (NP * NT);
        const int* src = (arg == 0) ? pred_ids : ((arg == 1) ? arg0_ids : arg1_ids);
        span_s[tid] = src[bs * NP * NT + rem];
    }
    if (tid < 32) {   // warp 0: ballot compaction of active rows (ascending)
        int base = 0;
        #pragma unroll
        for (int c = 0; c < NL / 32; c++) {
            int l = c * 32 + lane;
            int a = attn[bs * NL + l];
            unsigned m = __ballot_sync(0xFFFFFFFFu, a != 0);
            if (a != 0) alist[base + __popc(m & ((1u << lane) - 1u))] = l;
            base += __popc(m);
        }
        if (lane == 0) nact_s = base;
    }
    __syncthreads();

    const int nact = nact_s;

    // ---- phase 1a: parallel scan, thread = (pair, segment) ----
    {
        const int pair = tid >> 3;          // 0..47
        const int seg  = tid & 7;           // 0..7
        const int s0 = (nact * seg) / NSEG;
        const int s1 = (nact * (seg + 1)) / NSEG;
        int v0 = span_s[pair * NT + 0];
        int v1 = span_s[pair * NT + 1];
        int v2 = span_s[pair * NT + 2];
        int v3 = span_s[pair * NT + 3];
        int n = 0;
        #pragma unroll 1
        for (int i = s0; i < s1; i++) {
            int l = alist[i];
            int sid = sid_s[l];
            int c = (v0 == sid && v0 != PAD_ID)
                  + (v1 == sid && v1 != PAD_ID)
                  + (v2 == sid && v2 != PAD_ID)
                  + (v3 == sid && v3 != PAD_ID);
            if (c && n < SEGCAP)
                evseg[(pair * NSEG + seg) * SEGCAP + n++] = (unsigned short)(l | (c << 8));
        }
        cntseg[pair * NSEG + seg] = (unsigned char)n;
    }
    __syncthreads();

    // ---- phase 1b: 48 compactors (segment order = ascending = deterministic) ----
    if (tid < NPAIR) {
        int n = 0, den = 0;
        #pragma unroll 1
        for (int seg = 0; seg < NSEG; seg++) {
            int cnt = cntseg[tid * NSEG + seg];
            for (int k = 0; k < cnt; k++) {
                if (n < EVCAP) {
                    unsigned e = evseg[(tid * NSEG + seg) * SEGCAP + k];
                    events[tid * EVCAP + n++] = (unsigned short)e;
                    den += (int)(e >> 8);
                }
            }
        }
        nev_s[tid] = n;
        inv_s[tid] = (den > 0) ? 1.0f / (float)den : 0.0f;
    }
    __syncthreads();

    // ---- merged stream + gather loop ----
    const float4* eb = (const float4*)(emb + (size_t)bs * NL * ND) + cg;
    float*        outp = out + (size_t)NB * NS * ND;
    float4 s4 = make_float4(0.f, 0.f, 0.f, 0.f);
    const int clampi = (nact > 0) ? nact - 1 : 0;
    int pj = 0;                      // gather progress: 24 pairs per thread

    #pragma unroll 1
    for (int i0 = 0; i0 < nact; i0 += 8) {
        // stream loads (4 LDG.128, independent)
        float4 v[4];
        int    idx[4];
        #pragma unroll
        for (int k = 0; k < 4; k++) {
            idx[k] = i0 + 2 * k + rl;
            int l = alist[min(idx[k], clampi)];
            v[k] = __ldg(eb + (size_t)l * ND4);
        }

        // gather: fully process up to 2 pairs while stream loads are in flight
        #pragma unroll 1
        for (int rep = 0; rep < 2; rep++) {
            if (pj < NPAIR / NRL) {
                int pair = pj * NRL + rl;
                int ne   = nev_s[pair];
                float4 val = make_float4(0.f, 0.f, 0.f, 0.f);
                #pragma unroll 1
                for (int i = 0; i < ne; i += 2) {
                    unsigned e0 = events[pair * EVCAP + i];
                    bool ok1 = (i + 1) < ne;
                    unsigned e1 = events[pair * EVCAP + (ok1 ? i + 1 : i)];
                    int   l0 = (int)(e0 & 0xFFu); float c0 = (float)(e0 >> 8);
                    int   l1 = (int)(e1 & 0xFFu); float c1 = ok1 ? (float)(e1 >> 8) : 0.0f;
                    float4 w0 = __ldg(eb + (size_t)l0 * ND4);
                    float4 w1 = __ldg(eb + (size_t)l1 * ND4);
                    val.x = fmaf(c0, w0.x, fmaf(c1, w1.x, val.x));
                    val.y = fmaf(c0, w0.y, fmaf(c1, w1.y, val.y));
                    val.z = fmaf(c0, w0.z, fmaf(c1, w1.z, val.z));
                    val.w = fmaf(c0, w0.w, fmaf(c1, w1.w, val.w));
                }
                float inv = inv_s[pair];
                int arg = pair >> 4;
                int p   = pair & 15;
                float4* o4 = (float4*)(outp + (size_t)arg * NB * NS * NP * ND
                                            + (size_t)bs * NP * ND
                                            + (size_t)p * ND);
                o4[cg] = make_float4(val.x * inv, val.y * inv, val.z * inv, val.w * inv);
                pj++;
            }
        }

        // consume stream batch
        #pragma unroll
        for (int k = 0; k < 4; k++) {
            if (idx[k] < nact) {
                s4.x += v[k].x; s4.y += v[k].y; s4.z += v[k].z; s4.w += v[k].w;
            }
        }
    }

    // leftover gather pairs (small nact case)
    #pragma unroll 1
    while (pj < NPAIR / NRL) {
        int pair = pj * NRL + rl;
        int ne   = nev_s[pair];
        float4 val = make_float4(0.f, 0.f, 0.f, 0.f);
        #pragma unroll 1
        for (int i = 0; i < ne; i += 2) {
            unsigned e0 = events[pair * EVCAP + i];
            bool ok1 = (i + 1) < ne;
            unsigned e1 = events[pair * EVCAP + (ok1 ? i + 1 : i)];
            int   l0 = (int)(e0 & 0xFFu); float c0 = (float)(e0 >> 8);
            int   l1 = (int)(e1 & 0xFFu); float c1 = ok1 ? (float)(e1 >> 8) : 0.0f;
            float4 w0 = __ldg(eb + (size_t)l0 * ND4);
            float4 w1 = __ldg(eb + (size_t)l1 * ND4);
            val.x = fmaf(c0, w0.x, fmaf(c1, w1.x, val.x));
            val.y = fmaf(c0, w0.y, fmaf(c1, w1.y, val.y));
            val.z = fmaf(c0, w0.z, fmaf(c1, w1.z, val.z));
            val.w = fmaf(c0, w0.w, fmaf(c1, w1.w, val.w));
        }
        float inv = inv_s[pair];
        int arg = pair >> 4;
        int p   = pair & 15;
        float4* o4 = (float4*)(outp + (size_t)arg * NB * NS * NP * ND
                                    + (size_t)bs * NP * ND
                                    + (size_t)p * ND);
        o4[cg] = make_float4(val.x * inv, val.y * inv, val.z * inv, val.w * inv);
        pj++;
    }

    // ---- sentence average (block reduce at the very end) ----
    stage[rl * NCG + cg] = s4;
    __syncthreads();
    if (rl == 0) {
        float4 a = stage[cg], b = stage[NCG + cg];
        float tc = fmaxf((float)nact, 1.0f);
        float4 o;
        o.x = (a.x + b.x) / tc;
        o.y = (a.y + b.y) / tc;
        o.z = (a.z + b.z) / tc;
        o.w = (a.w + b.w) / tc;
        ((float4*)(out + (size_t)bs * ND))[cg] = o;
    }
}

extern "C" void kernel_launch(void* const* d_in, const int* in_sizes, int n_in,
                              void* d_out, int out_size)
{
    const int*   sent_ids = (const int*)d_in[0];
    const int*   attn     = (const int*)d_in[1];
    const int*   pred_ids = (const int*)d_in[2];
    const int*   arg0_ids = (const int*)d_in[3];
    const int*   arg1_ids = (const int*)d_in[4];
    const float* emb      = (const float*)d_in[5];
    float*       out      = (float*)d_out;

    dim3 grid(NB * NS);
    dim3 block(NTHREADS);
    srl_kernel<<<grid, block>>>(sent_ids, attn, pred_ids, arg0_ids,
                                arg1_ids, emb, out);
}